// round 1
// baseline (speedup 1.0000x reference)
#include <cuda_runtime.h>

#define BSZ  2048
#define TLEN 12
#define HIDD 1024
#define NCLS 51
#define MROWS (TLEN * BSZ)   // 24576

// ---------------- scratch (device globals; no allocation allowed) -----------
__device__ float g_U [(size_t)MROWS * 4096];   // GEMM output, reused per layer
__device__ float g_h1[(size_t)MROWS * HIDD];
__device__ float g_h2[(size_t)MROWS * HIDD];
__device__ float g_g [(size_t)BSZ   * HIDD];   // time-summed h3

// ---------------- packed f32x2 helpers (sm_103a FFMA2) ----------------------
__device__ __forceinline__ unsigned long long pack2(float lo, float hi) {
    unsigned long long r;
    asm("mov.b64 %0, {%1,%2};" : "=l"(r) : "f"(lo), "f"(hi));
    return r;
}
__device__ __forceinline__ float2 unpack2(unsigned long long v) {
    float2 r;
    asm("mov.b64 {%0,%1}, %2;" : "=f"(r.x), "=f"(r.y) : "l"(v));
    return r;
}
__device__ __forceinline__ unsigned long long fma2(unsigned long long a,
                                                   unsigned long long b,
                                                   unsigned long long c) {
    unsigned long long d;
    asm("fma.rn.f32x2 %0, %1, %2, %3;" : "=l"(d) : "l"(a), "l"(b), "l"(c));
    return d;
}

// ---------------- fp32 tiled GEMM: C[M,N] = A[M,K] @ B[K,N] -----------------
// BM=BN=128, BK=8, 256 threads, 8x8 per thread (split 4+4 rows/cols to avoid
// smem bank conflicts). remap!=0: A row m=t*BSZ+b reads x at row (b*TLEN+t)
// (handles the (B,T,D)->(T,B,D) transpose for layer 0 for free).
__global__ __launch_bounds__(256, 2)
void gemm_k(const float* __restrict__ A, const float* __restrict__ B,
            float* __restrict__ C, int N, int K, int remap)
{
    __shared__ float As[8][128];
    __shared__ float Bs[8][128];

    const int tid = threadIdx.x;
    const int tx = tid & 15, ty = tid >> 4;
    const long bm = (long)blockIdx.y * 128;
    const long bn = (long)blockIdx.x * 128;

    // A staging: each thread loads float4; a_row 0..127, a_col {0,4}
    const int a_row = tid >> 1;
    const int a_col = (tid & 1) * 4;
    long gr = bm + a_row;
    long aoff;
    if (remap) {
        long bb = gr % BSZ, tt = gr / BSZ;
        aoff = (bb * TLEN + tt) * (long)K;
    } else {
        aoff = gr * (long)K;
    }
    const float* Ap = A + aoff + a_col;

    // B staging: b_row 0..7, b_col multiples of 4 (coalesced float4)
    const int b_row = tid >> 5;
    const int b_col = (tid & 31) * 4;
    const float* Bp = B + (long)b_row * N + bn + b_col;

    unsigned long long acc[8][4];
#pragma unroll
    for (int i = 0; i < 8; i++)
#pragma unroll
        for (int j = 0; j < 4; j++) acc[i][j] = 0ULL;  // (+0.f, +0.f)

    for (int k0 = 0; k0 < K; k0 += 8) {
        float4 av = *reinterpret_cast<const float4*>(Ap + k0);
        As[a_col + 0][a_row] = av.x;
        As[a_col + 1][a_row] = av.y;
        As[a_col + 2][a_row] = av.z;
        As[a_col + 3][a_row] = av.w;
        *reinterpret_cast<float4*>(&Bs[b_row][b_col]) =
            *reinterpret_cast<const float4*>(Bp + (long)k0 * N);
        __syncthreads();

#pragma unroll
        for (int kk = 0; kk < 8; kk++) {
            float4 a0 = *reinterpret_cast<const float4*>(&As[kk][ty * 4]);
            float4 a1 = *reinterpret_cast<const float4*>(&As[kk][64 + ty * 4]);
            float4 b0 = *reinterpret_cast<const float4*>(&Bs[kk][tx * 4]);
            float4 b1 = *reinterpret_cast<const float4*>(&Bs[kk][64 + tx * 4]);
            float ar[8] = {a0.x, a0.y, a0.z, a0.w, a1.x, a1.y, a1.z, a1.w};
            unsigned long long bp[4];
            bp[0] = pack2(b0.x, b0.y);
            bp[1] = pack2(b0.z, b0.w);
            bp[2] = pack2(b1.x, b1.y);
            bp[3] = pack2(b1.z, b1.w);
#pragma unroll
            for (int i = 0; i < 8; i++) {
                unsigned long long aa = pack2(ar[i], ar[i]);
#pragma unroll
                for (int j = 0; j < 4; j++) acc[i][j] = fma2(aa, bp[j], acc[i][j]);
            }
        }
        __syncthreads();
    }

#pragma unroll
    for (int i = 0; i < 8; i++) {
        long row = bm + (i < 4 ? ty * 4 + i : 64 + ty * 4 + (i - 4));
        float* Cp = C + row * N + bn;
        float2 v0 = unpack2(acc[i][0]), v1 = unpack2(acc[i][1]);
        float2 v2 = unpack2(acc[i][2]), v3 = unpack2(acc[i][3]);
        *reinterpret_cast<float4*>(Cp + tx * 4)      = make_float4(v0.x, v0.y, v1.x, v1.y);
        *reinterpret_cast<float4*>(Cp + 64 + tx * 4) = make_float4(v2.x, v2.y, v3.x, v3.y);
    }
}

// ---------------- SRU recurrence: one thread per (b,d), scan over T ---------
__global__ __launch_bounds__(256)
void sru_k(const float* __restrict__ U, const float* __restrict__ resid_in,
           const float* __restrict__ vc, const float* __restrict__ bvec,
           float* __restrict__ h_out, int kcols)
{
    const float SCALE_X = 1.7320508075688772f;  // sqrt(1 + e^0 * 2)
    int idx = blockIdx.x * blockDim.x + threadIdx.x;   // over BSZ*HIDD
    int d = idx & (HIDD - 1);
    int b = idx >> 10;
    float vf = vc[d],        vr = vc[HIDD + d];
    float bf = bvec[d],      br = bvec[HIDD + d];
    const long kH = (long)kcols * HIDD;
    long ubase = (long)b * kH + d;          // row (t=0, b)
    long hbase = (long)b * HIDD + d;
    const long ustride = (long)BSZ * kH;
    const long hstride = (long)BSZ * HIDD;
    float c = 0.f;
#pragma unroll
    for (int t = 0; t < TLEN; t++) {
        float u0 = U[ubase];
        float u1 = U[ubase + HIDD];
        float u2 = U[ubase + 2 * HIDD];
        float xr = (kcols == 4) ? U[ubase + 3 * HIDD] : resid_in[hbase];
        float f = 1.f / (1.f + __expf(-(u1 + vf * c + bf)));
        c = f * c + (1.f - f) * u0;
        float r = 1.f / (1.f + __expf(-(u2 + vr * c + br)));
        float h = r * tanhf(c) + (1.f - r) * xr * SCALE_X;
        h_out[hbase] = h;
        ubase += ustride;
        hbase += hstride;
    }
}

// ---------------- time-sum: g[b][h] = sum_t h3[t][b][h] ---------------------
__global__ __launch_bounds__(256)
void tsum_k(const float* __restrict__ h, float* __restrict__ g)
{
    long idx = (long)blockIdx.x * blockDim.x + threadIdx.x;  // b*HIDD + d
    float s = 0.f;
    long off = idx;
#pragma unroll
    for (int t = 0; t < TLEN; t++) {
        s += h[off];
        off += (long)BSZ * HIDD;
    }
    g[idx] = s;
}

// ---------------- FC head: out[b][c] = g[b]·w[:,c]/T + bias[c] --------------
__global__ __launch_bounds__(128)
void fc_k(const float* __restrict__ g, const float* __restrict__ w,
          const float* __restrict__ bias, float* __restrict__ out)
{
    __shared__ float gs[HIDD];
    int b = blockIdx.x;
    for (int i = threadIdx.x; i < HIDD; i += blockDim.x)
        gs[i] = g[(long)b * HIDD + i];
    __syncthreads();
    int c = threadIdx.x;
    if (c < NCLS) {
        float s = 0.f;
#pragma unroll 8
        for (int hh = 0; hh < HIDD; hh++) s += gs[hh] * w[hh * NCLS + c];
        out[(long)b * NCLS + c] = s * (1.f / TLEN) + bias[c];
    }
}

// ---------------- launch ----------------------------------------------------
extern "C" void kernel_launch(void* const* d_in, const int* in_sizes, int n_in,
                              void* d_out, int out_size)
{
    const float* x    = (const float*)d_in[0];
    const float* W0   = (const float*)d_in[1];
    const float* W1   = (const float*)d_in[2];
    const float* W2   = (const float*)d_in[3];
    const float* vc0  = (const float*)d_in[4];
    const float* vc1  = (const float*)d_in[5];
    const float* vc2  = (const float*)d_in[6];
    const float* b0   = (const float*)d_in[7];
    const float* b1   = (const float*)d_in[8];
    const float* b2   = (const float*)d_in[9];
    const float* fcw  = (const float*)d_in[10];
    const float* fcb  = (const float*)d_in[11];
    float* out = (float*)d_out;

    float *U, *h1, *h2, *gg;
    cudaGetSymbolAddress((void**)&U,  g_U);
    cudaGetSymbolAddress((void**)&h1, g_h1);
    cudaGetSymbolAddress((void**)&h2, g_h2);
    cudaGetSymbolAddress((void**)&gg, g_g);

    const int sruBlocks = (BSZ * HIDD) / 256;

    // Layer 0: U = x(T,B,512 via remap) @ W0(512,4096)
    {
        dim3 grid(4096 / 128, MROWS / 128);
        gemm_k<<<grid, 256>>>(x, W0, U, 4096, 512, 1);
        sru_k<<<sruBlocks, 256>>>(U, nullptr, vc0, b0, h1, 4);
    }
    // Layer 1: U = h1 @ W1(1024,3072)
    {
        dim3 grid(3072 / 128, MROWS / 128);
        gemm_k<<<grid, 256>>>(h1, W1, U, 3072, 1024, 0);
        sru_k<<<sruBlocks, 256>>>(U, h1, vc1, b1, h2, 3);
    }
    // Layer 2: U = h2 @ W2(1024,3072)
    {
        dim3 grid(3072 / 128, MROWS / 128);
        gemm_k<<<grid, 256>>>(h2, W2, U, 3072, 1024, 0);
        sru_k<<<sruBlocks, 256>>>(U, h2, vc2, b2, h1, 3);
    }
    // Head: time-sum then tiny GEMM + bias, mean over T
    tsum_k<<<(BSZ * HIDD) / 256, 256>>>(h1, gg);
    fc_k<<<BSZ, 128>>>(gg, fcw, fcb, out);
}

// round 4
// speedup vs baseline: 3.4539x; 3.4539x over previous
#include <cuda_runtime.h>
#include <cuda_fp16.h>
#include <cstdint>

#define BSZ  2048
#define TLEN 12
#define HIDD 1024
#define NCLS 51
#define MROWS (TLEN * BSZ)   // 24576

// GEMM tiling
#define BM 128
#define BN 256
#define BK 32                       // halfs per K-chunk
#define NSTAGE 3
#define A_STAGE_BYTES 16384         // 128 rows x 128B (hi|lo)
#define B_STAGE_BYTES 32768         // 256 rows x 128B (hi|lo)
#define STAGE_BYTES (A_STAGE_BYTES + B_STAGE_BYTES)
#define SMEM_TOTAL (NSTAGE * STAGE_BYTES)

// ---------------- scratch (device globals; no allocation allowed) -----------
__device__ __align__(16) float  g_U [(size_t)MROWS * 4096];
__device__ __align__(16) float  g_h1[(size_t)MROWS * HIDD];
__device__ __align__(16) float  g_h2[(size_t)MROWS * HIDD];
__device__ __align__(16) float  g_g [(size_t)BSZ   * HIDD];
__device__ __align__(16) __half g_ahi[(size_t)MROWS * HIDD];
__device__ __align__(16) __half g_alo[(size_t)MROWS * HIDD];
__device__ __align__(16) __half g_whi[(size_t)4096 * HIDD];   // Wt hi [N,K]
__device__ __align__(16) __half g_wlo[(size_t)4096 * HIDD];   // Wt lo [N,K]

// ---------------- helpers ----------------------------------------------------
__device__ __forceinline__ uint32_t smem_u32(const void* p) {
    uint32_t a;
    asm("{ .reg .u64 t; cvta.to.shared.u64 t, %1; cvt.u32.u64 %0, t; }" : "=r"(a) : "l"(p));
    return a;
}
#define SWZ(o) ((uint32_t)(o) ^ ((((uint32_t)(o)) >> 3) & 0x70))

__device__ __forceinline__ void cp16(uint32_t s, const void* g) {
    asm volatile("cp.async.cg.shared.global [%0], [%1], 16;" :: "r"(s), "l"(g));
}
#define CP_COMMIT() asm volatile("cp.async.commit_group;" ::: "memory")
#define CP_WAIT1()  asm volatile("cp.async.wait_group 1;" ::: "memory")

#define LDSM4(r, addr) \
    asm volatile("ldmatrix.sync.aligned.m8n8.x4.shared.b16 {%0,%1,%2,%3}, [%4];" \
        : "=r"((r)[0]), "=r"((r)[1]), "=r"((r)[2]), "=r"((r)[3]) : "r"(addr))

#define MMA(d, a, b) \
    asm volatile("mma.sync.aligned.m16n8k16.row.col.f32.f16.f16.f32 " \
        "{%0,%1,%2,%3}, {%4,%5,%6,%7}, {%8,%9}, {%0,%1,%2,%3};" \
        : "+f"((d)[0]), "+f"((d)[1]), "+f"((d)[2]), "+f"((d)[3]) \
        : "r"((a)[0]), "r"((a)[1]), "r"((a)[2]), "r"((a)[3]), "r"((b)[0]), "r"((b)[1]))

__device__ __forceinline__ void split2h(float v, __half& hi, __half& lo) {
    hi = __float2half_rn(v);
    lo = __float2half_rn(v - __half2float(hi));
}

// ---------------- mma.sync fp16-split GEMM -----------------------------------
// C[M,N] = A[M,K] @ Wt[N,K]^T ; A,Wt given as hi/lo fp16. grid=(N/BN, M/BM), 512 thr.
__global__ __launch_bounds__(512, 1)
void gemm_tc(const __half* __restrict__ Ahi, const __half* __restrict__ Alo,
             const __half* __restrict__ Bhi, const __half* __restrict__ Blo,
             float* __restrict__ C, int N, int K)
{
    extern __shared__ char smem[];
    const int tid = threadIdx.x, lane = tid & 31, wid = tid >> 5;
    const uint32_t sb = smem_u32(smem);
    const size_t bm = (size_t)blockIdx.y * BM;
    const size_t bn = (size_t)blockIdx.x * BN;
    const int nch = K >> 5;

    // warp -> 64x32 sub-tile
    const int m0w = (wid & 1) * 64;
    const int n0w = (wid >> 1) * 32;
    // ldmatrix lane maps
    const int rA = lane & 15;
    const int cA = (lane & 16) ? 16 : 0;
    const int rB = (lane & 7) | ((lane & 16) >> 1);
    const int cB = (lane & 8) ? 16 : 0;

    float acc[4][4][4];
#pragma unroll
    for (int i = 0; i < 4; i++)
#pragma unroll
        for (int j = 0; j < 4; j++)
#pragma unroll
            for (int q = 0; q < 4; q++) acc[i][j][q] = 0.f;

    // stage loader
    auto loadStage = [&](int c, int s) {
        if (c >= nch) return;
        const int k0 = c << 5;
        const uint32_t sa = sb + s * STAGE_BYTES;
        const uint32_t sB = sa + A_STAGE_BYTES;
#pragma unroll
        for (int ii = 0; ii < 2; ii++) {
            int i = tid + ii * 512;
            int row = i >> 3, sub = i & 7;
            const __half* gp = (sub < 4 ? Ahi : Alo) + (bm + row) * (size_t)K + k0 + (sub & 3) * 8;
            cp16(sa + SWZ(row * 128 + sub * 16), gp);
        }
#pragma unroll
        for (int ii = 0; ii < 4; ii++) {
            int i = tid + ii * 512;
            int row = i >> 3, sub = i & 7;
            const __half* gp = (sub < 4 ? Bhi : Blo) + (bn + row) * (size_t)K + k0 + (sub & 3) * 8;
            cp16(sB + SWZ(row * 128 + sub * 16), gp);
        }
    };

    loadStage(0, 0); CP_COMMIT();
    loadStage(1, 1); CP_COMMIT();

    int stage = 0;
    for (int c = 0; c < nch; c++) {
        CP_WAIT1();
        __syncthreads();
        // prefetch into the stage freed two iterations ago: (stage+2) mod NSTAGE
        {
            int ws = stage + 2;
            if (ws >= NSTAGE) ws -= NSTAGE;
            loadStage(c + 2, ws);
        }
        CP_COMMIT();

        const uint32_t sa = sb + stage * STAGE_BYTES;
        const uint32_t sB = sa + A_STAGE_BYTES;
        stage = (stage + 1 == NSTAGE) ? 0 : stage + 1;

#pragma unroll
        for (int ks = 0; ks < 2; ks++) {
            uint32_t a[4][4], b[4][2];
            // ---- term 1: Ahi * Bhi ----
#pragma unroll
            for (int mt = 0; mt < 4; mt++)
                LDSM4(a[mt], sa + SWZ((m0w + mt * 16 + rA) * 128 + ks * 32 + cA));
#pragma unroll
            for (int np = 0; np < 2; np++) {
                uint32_t r4[4];
                LDSM4(r4, sB + SWZ((n0w + np * 16 + rB) * 128 + ks * 32 + cB));
                b[np * 2][0] = r4[0]; b[np * 2][1] = r4[1];
                b[np * 2 + 1][0] = r4[2]; b[np * 2 + 1][1] = r4[3];
            }
#pragma unroll
            for (int mt = 0; mt < 4; mt++)
#pragma unroll
                for (int nt = 0; nt < 4; nt++) MMA(acc[mt][nt], a[mt], b[nt]);

            // ---- term 2: Alo * Bhi ----
#pragma unroll
            for (int mt = 0; mt < 4; mt++)
                LDSM4(a[mt], sa + SWZ((m0w + mt * 16 + rA) * 128 + ks * 32 + cA + 64));
#pragma unroll
            for (int mt = 0; mt < 4; mt++)
#pragma unroll
                for (int nt = 0; nt < 4; nt++) MMA(acc[mt][nt], a[mt], b[nt]);

            // ---- term 3: Ahi * Blo ----
#pragma unroll
            for (int mt = 0; mt < 4; mt++)
                LDSM4(a[mt], sa + SWZ((m0w + mt * 16 + rA) * 128 + ks * 32 + cA));
#pragma unroll
            for (int np = 0; np < 2; np++) {
                uint32_t r4[4];
                LDSM4(r4, sB + SWZ((n0w + np * 16 + rB) * 128 + ks * 32 + cB + 64));
                b[np * 2][0] = r4[0]; b[np * 2][1] = r4[1];
                b[np * 2 + 1][0] = r4[2]; b[np * 2 + 1][1] = r4[3];
            }
#pragma unroll
            for (int mt = 0; mt < 4; mt++)
#pragma unroll
                for (int nt = 0; nt < 4; nt++) MMA(acc[mt][nt], a[mt], b[nt]);
        }
    }

    // epilogue
    const int g = lane >> 2, t = lane & 3;
#pragma unroll
    for (int mt = 0; mt < 4; mt++) {
#pragma unroll
        for (int nt = 0; nt < 4; nt++) {
            size_t row = bm + m0w + mt * 16 + g;
            size_t col = bn + n0w + nt * 8 + t * 2;
            *(float2*)(C + row * (size_t)N + col) =
                make_float2(acc[mt][nt][0], acc[mt][nt][1]);
            *(float2*)(C + (row + 8) * (size_t)N + col) =
                make_float2(acc[mt][nt][2], acc[mt][nt][3]);
        }
    }
}

// ---------------- x -> hi/lo fp16 with (B,T)->(T,B) remap --------------------
__global__ __launch_bounds__(256)
void conv_x(const float* __restrict__ x, __half* __restrict__ hi, __half* __restrict__ lo)
{
    size_t i = (size_t)blockIdx.x * blockDim.x + threadIdx.x;  // over T*B*512
    int d = i & 511;
    size_t r = i >> 9;
    int b = (int)(r & (BSZ - 1));
    int t = (int)(r >> 11);
    float v = x[((size_t)b * TLEN + t) * 512 + d];
    __half h, l; split2h(v, h, l);
    hi[i] = h; lo[i] = l;
}

// ---------------- W[K,N] -> Wt hi/lo [N,K] (tiled transpose) -----------------
__global__ __launch_bounds__(256)
void conv_wt(const float* __restrict__ W, __half* __restrict__ Whi,
             __half* __restrict__ Wlo, int K, int N)
{
    __shared__ float t[32][33];
    const int n0 = blockIdx.x * 32, k0 = blockIdx.y * 32;
    const int tx = threadIdx.x & 31, ty = threadIdx.x >> 5;  // 32x8
#pragma unroll
    for (int j = 0; j < 32; j += 8)
        t[ty + j][tx] = W[(size_t)(k0 + ty + j) * N + n0 + tx];
    __syncthreads();
#pragma unroll
    for (int j = 0; j < 32; j += 8) {
        float v = t[tx][ty + j];
        __half h, l; split2h(v, h, l);
        size_t o = (size_t)(n0 + ty + j) * K + k0 + tx;
        Whi[o] = h; Wlo[o] = l;
    }
}

// ---------------- SRU recurrence (emits fp32 h + hi/lo fp16) -----------------
__global__ __launch_bounds__(256)
void sru_k(const float* __restrict__ U, const float* __restrict__ resid_in,
           const float* __restrict__ vc, const float* __restrict__ bvec,
           float* __restrict__ h_out, int kcols,
           __half* __restrict__ hhi, __half* __restrict__ hlo)
{
    const float SCALE_X = 1.7320508075688772f;
    int idx = blockIdx.x * blockDim.x + threadIdx.x;
    int d = idx & (HIDD - 1);
    int b = idx >> 10;
    float vf = vc[d],   vr = vc[HIDD + d];
    float bf = bvec[d], br = bvec[HIDD + d];
    const long kH = (long)kcols * HIDD;
    long ubase = (long)b * kH + d;
    long hbase = (long)b * HIDD + d;
    const long ustride = (long)BSZ * kH;
    const long hstride = (long)BSZ * HIDD;
    float c = 0.f;
#pragma unroll
    for (int t = 0; t < TLEN; t++) {
        float u0 = U[ubase];
        float u1 = U[ubase + HIDD];
        float u2 = U[ubase + 2 * HIDD];
        float xr = (kcols == 4) ? U[ubase + 3 * HIDD] : resid_in[hbase];
        float f = 1.f / (1.f + __expf(-(u1 + vf * c + bf)));
        c = f * c + (1.f - f) * u0;
        float r = 1.f / (1.f + __expf(-(u2 + vr * c + br)));
        float h = r * tanhf(c) + (1.f - r) * xr * SCALE_X;
        h_out[hbase] = h;
        if (hhi) {
            __half hh, hl; split2h(h, hh, hl);
            hhi[hbase] = hh; hlo[hbase] = hl;
        }
        ubase += ustride;
        hbase += hstride;
    }
}

// ---------------- time-sum ---------------------------------------------------
__global__ __launch_bounds__(256)
void tsum_k(const float* __restrict__ h, float* __restrict__ g)
{
    long idx = (long)blockIdx.x * blockDim.x + threadIdx.x;
    float s = 0.f;
    long off = idx;
#pragma unroll
    for (int t = 0; t < TLEN; t++) { s += h[off]; off += (long)BSZ * HIDD; }
    g[idx] = s;
}

// ---------------- FC head ----------------------------------------------------
__global__ __launch_bounds__(128)
void fc_k(const float* __restrict__ g, const float* __restrict__ w,
          const float* __restrict__ bias, float* __restrict__ out)
{
    __shared__ float gs[HIDD];
    int b = blockIdx.x;
    for (int i = threadIdx.x; i < HIDD; i += blockDim.x)
        gs[i] = g[(long)b * HIDD + i];
    __syncthreads();
    int c = threadIdx.x;
    if (c < NCLS) {
        float s = 0.f;
#pragma unroll 8
        for (int hh = 0; hh < HIDD; hh++) s += gs[hh] * w[hh * NCLS + c];
        out[(long)b * NCLS + c] = s * (1.f / TLEN) + bias[c];
    }
}

// ---------------- launch -----------------------------------------------------
extern "C" void kernel_launch(void* const* d_in, const int* in_sizes, int n_in,
                              void* d_out, int out_size)
{
    const float* x    = (const float*)d_in[0];
    const float* W0   = (const float*)d_in[1];
    const float* W1   = (const float*)d_in[2];
    const float* W2   = (const float*)d_in[3];
    const float* vc0  = (const float*)d_in[4];
    const float* vc1  = (const float*)d_in[5];
    const float* vc2  = (const float*)d_in[6];
    const float* b0   = (const float*)d_in[7];
    const float* b1   = (const float*)d_in[8];
    const float* b2   = (const float*)d_in[9];
    const float* fcw  = (const float*)d_in[10];
    const float* fcb  = (const float*)d_in[11];
    float* out = (float*)d_out;

    float *U, *h1, *h2, *gg;
    __half *ahi, *alo, *whi, *wlo;
    cudaGetSymbolAddress((void**)&U,   g_U);
    cudaGetSymbolAddress((void**)&h1,  g_h1);
    cudaGetSymbolAddress((void**)&h2,  g_h2);
    cudaGetSymbolAddress((void**)&gg,  g_g);
    cudaGetSymbolAddress((void**)&ahi, g_ahi);
    cudaGetSymbolAddress((void**)&alo, g_alo);
    cudaGetSymbolAddress((void**)&whi, g_whi);
    cudaGetSymbolAddress((void**)&wlo, g_wlo);

    cudaFuncSetAttribute(gemm_tc, cudaFuncAttributeMaxDynamicSharedMemorySize, SMEM_TOTAL);

    const int sruBlocks = (BSZ * HIDD) / 256;

    // Layer 0: x(T,B,512) @ W0(512,4096)
    conv_x<<<(TLEN * BSZ * 512) / 256, 256>>>(x, ahi, alo);
    conv_wt<<<dim3(4096 / 32, 512 / 32), 256>>>(W0, whi, wlo, 512, 4096);
    gemm_tc<<<dim3(4096 / BN, MROWS / BM), 512, SMEM_TOTAL>>>(ahi, alo, whi, wlo, U, 4096, 512);
    sru_k<<<sruBlocks, 256>>>(U, nullptr, vc0, b0, h1, 4, ahi, alo);

    // Layer 1: h1 @ W1(1024,3072)
    conv_wt<<<dim3(3072 / 32, 1024 / 32), 256>>>(W1, whi, wlo, 1024, 3072);
    gemm_tc<<<dim3(3072 / BN, MROWS / BM), 512, SMEM_TOTAL>>>(ahi, alo, whi, wlo, U, 3072, 1024);
    sru_k<<<sruBlocks, 256>>>(U, h1, vc1, b1, h2, 3, ahi, alo);

    // Layer 2: h2 @ W2(1024,3072)
    conv_wt<<<dim3(3072 / 32, 1024 / 32), 256>>>(W2, whi, wlo, 1024, 3072);
    gemm_tc<<<dim3(3072 / BN, MROWS / BM), 512, SMEM_TOTAL>>>(ahi, alo, whi, wlo, U, 3072, 1024);
    sru_k<<<sruBlocks, 256>>>(U, h2, vc2, b2, h1, 3, nullptr, nullptr);

    // Head
    tsum_k<<<(BSZ * HIDD) / 256, 256>>>(h1, gg);
    fc_k<<<BSZ, 128>>>(gg, fcw, fcb, out);
}

// round 5
// speedup vs baseline: 5.4884x; 1.5890x over previous
#include <cuda_runtime.h>
#include <cuda_fp16.h>
#include <cstdint>

#define BSZ  2048
#define TLEN 12
#define HIDD 1024
#define NCLS 51
#define MROWS (TLEN * BSZ)   // 24576

// GEMM tiling
#define BM 128
#define BN 256
#define BK 64                       // halfs per K-chunk (one 128B row)
#define NSTAGE 3
#define A_STAGE_BYTES 16384         // 128 rows x 128B, per array (hi, lo)
#define B_STAGE_BYTES 32768         // 256 rows x 128B
#define STAGE_BYTES (2 * A_STAGE_BYTES + B_STAGE_BYTES)   // 64KB
#define SMEM_TOTAL (NSTAGE * STAGE_BYTES)                 // 192KB

// ---------------- scratch (device globals; no allocation allowed) -----------
__device__ __align__(16) float  g_U [(size_t)MROWS * 4096];
__device__ __align__(16) float  g_g [(size_t)BSZ   * HIDD];
__device__ __align__(16) __half g_ahi[(size_t)MROWS * HIDD];
__device__ __align__(16) __half g_alo[(size_t)MROWS * HIDD];
__device__ __align__(16) __half g_wh [(size_t)4096 * HIDD];   // Wt fp16 [N,K]

// ---------------- helpers ----------------------------------------------------
__device__ __forceinline__ uint32_t smem_u32(const void* p) {
    uint32_t a;
    asm("{ .reg .u64 t; cvta.to.shared.u64 t, %1; cvt.u32.u64 %0, t; }" : "=r"(a) : "l"(p));
    return a;
}
#define SWZ(o) ((uint32_t)(o) ^ ((((uint32_t)(o)) >> 3) & 0x70))

__device__ __forceinline__ void cp16(uint32_t s, const void* g) {
    asm volatile("cp.async.cg.shared.global [%0], [%1], 16;" :: "r"(s), "l"(g));
}
#define CP_COMMIT() asm volatile("cp.async.commit_group;" ::: "memory")
#define CP_WAIT1()  asm volatile("cp.async.wait_group 1;" ::: "memory")

#define LDSM4(r, addr) \
    asm volatile("ldmatrix.sync.aligned.m8n8.x4.shared.b16 {%0,%1,%2,%3}, [%4];" \
        : "=r"((r)[0]), "=r"((r)[1]), "=r"((r)[2]), "=r"((r)[3]) : "r"(addr))

#define MMA(d, a, b) \
    asm volatile("mma.sync.aligned.m16n8k16.row.col.f32.f16.f16.f32 " \
        "{%0,%1,%2,%3}, {%4,%5,%6,%7}, {%8,%9}, {%0,%1,%2,%3};" \
        : "+f"((d)[0]), "+f"((d)[1]), "+f"((d)[2]), "+f"((d)[3]) \
        : "r"((a)[0]), "r"((a)[1]), "r"((a)[2]), "r"((a)[3]), "r"((b)[0]), "r"((b)[1]))

__device__ __forceinline__ void split2h(float v, __half& hi, __half& lo) {
    hi = __float2half_rn(v);
    lo = __float2half_rn(v - __half2float(hi));
}

// ---------------- mma.sync 2-term GEMM ---------------------------------------
// C[M,N] = (Ahi+Alo)[M,K] @ Bh[N,K]^T.  grid=(N/BN, M/BM), 512 threads.
__global__ __launch_bounds__(512, 1)
void gemm_tc(const __half* __restrict__ Ahi, const __half* __restrict__ Alo,
             const __half* __restrict__ Bh, float* __restrict__ C, int N, int K)
{
    extern __shared__ char smem[];
    const int tid = threadIdx.x, lane = tid & 31, wid = tid >> 5;
    const uint32_t sb = smem_u32(smem);
    const size_t bm = (size_t)blockIdx.y * BM;
    const size_t bn = (size_t)blockIdx.x * BN;
    const int nch = K >> 6;

    // warp -> 64x32 sub-tile
    const int m0w = (wid & 1) * 64;
    const int n0w = (wid >> 1) * 32;
    // ldmatrix lane maps (validated in R4)
    const int rA = lane & 15;
    const int cA = (lane & 16) ? 16 : 0;
    const int rB = (lane & 7) | ((lane & 16) >> 1);
    const int cB = (lane & 8) ? 16 : 0;

    float acc[4][4][4];
#pragma unroll
    for (int i = 0; i < 4; i++)
#pragma unroll
        for (int j = 0; j < 4; j++)
#pragma unroll
            for (int q = 0; q < 4; q++) acc[i][j][q] = 0.f;

    auto loadStage = [&](int c, int s) {
        if (c >= nch) return;
        const int k0 = c << 6;
        const uint32_t sa = sb + s * STAGE_BYTES;           // Ahi
        const uint32_t sB = sa + 2 * A_STAGE_BYTES;         // B
        // A: 2 arrays x 128 rows x 8 chunks = 2048 cp16
#pragma unroll
        for (int ii = 0; ii < 4; ii++) {
            int i = tid + ii * 512;
            int arr = i >> 10, rem = i & 1023;
            int row = rem >> 3, c16 = rem & 7;
            const __half* gp = (arr ? Alo : Ahi) + (bm + row) * (size_t)K + k0 + c16 * 8;
            cp16(sa + arr * A_STAGE_BYTES + SWZ(row * 128 + c16 * 16), gp);
        }
        // B: 256 rows x 8 chunks = 2048 cp16
#pragma unroll
        for (int ii = 0; ii < 4; ii++) {
            int i = tid + ii * 512;
            int row = i >> 3, c16 = i & 7;
            const __half* gp = Bh + (bn + row) * (size_t)K + k0 + c16 * 8;
            cp16(sB + SWZ(row * 128 + c16 * 16), gp);
        }
    };

    loadStage(0, 0); CP_COMMIT();
    loadStage(1, 1); CP_COMMIT();

    int stage = 0;
    for (int c = 0; c < nch; c++) {
        CP_WAIT1();
        __syncthreads();
        {
            int ws = stage + 2;
            if (ws >= NSTAGE) ws -= NSTAGE;
            loadStage(c + 2, ws);
        }
        CP_COMMIT();

        const uint32_t sa = sb + stage * STAGE_BYTES;
        const uint32_t sB = sa + 2 * A_STAGE_BYTES;
        stage = (stage + 1 == NSTAGE) ? 0 : stage + 1;

#pragma unroll
        for (int ks = 0; ks < 4; ks++) {
            uint32_t a[4][4], b[4][2];
#pragma unroll
            for (int np = 0; np < 2; np++) {
                uint32_t r4[4];
                LDSM4(r4, sB + SWZ((n0w + np * 16 + rB) * 128 + ks * 32 + cB));
                b[np * 2][0] = r4[0]; b[np * 2][1] = r4[1];
                b[np * 2 + 1][0] = r4[2]; b[np * 2 + 1][1] = r4[3];
            }
            // term 1: Ahi * B
#pragma unroll
            for (int mt = 0; mt < 4; mt++)
                LDSM4(a[mt], sa + SWZ((m0w + mt * 16 + rA) * 128 + ks * 32 + cA));
#pragma unroll
            for (int mt = 0; mt < 4; mt++)
#pragma unroll
                for (int nt = 0; nt < 4; nt++) MMA(acc[mt][nt], a[mt], b[nt]);
            // term 2: Alo * B (reuse b frags, overwrite a frags)
#pragma unroll
            for (int mt = 0; mt < 4; mt++)
                LDSM4(a[mt], sa + A_STAGE_BYTES + SWZ((m0w + mt * 16 + rA) * 128 + ks * 32 + cA));
#pragma unroll
            for (int mt = 0; mt < 4; mt++)
#pragma unroll
                for (int nt = 0; nt < 4; nt++) MMA(acc[mt][nt], a[mt], b[nt]);
        }
    }

    // epilogue
    const int g = lane >> 2, t = lane & 3;
#pragma unroll
    for (int mt = 0; mt < 4; mt++) {
#pragma unroll
        for (int nt = 0; nt < 4; nt++) {
            size_t row = bm + m0w + mt * 16 + g;
            size_t col = bn + n0w + nt * 8 + t * 2;
            *(float2*)(C + row * (size_t)N + col) =
                make_float2(acc[mt][nt][0], acc[mt][nt][1]);
            *(float2*)(C + (row + 8) * (size_t)N + col) =
                make_float2(acc[mt][nt][2], acc[mt][nt][3]);
        }
    }
}

// ---------------- x -> hi/lo fp16 with (B,T)->(T,B) remap --------------------
__global__ __launch_bounds__(256)
void conv_x(const float* __restrict__ x, __half* __restrict__ hi, __half* __restrict__ lo)
{
    size_t i = (size_t)blockIdx.x * blockDim.x + threadIdx.x;  // over T*B*512
    int d = i & 511;
    size_t r = i >> 9;
    int b = (int)(r & (BSZ - 1));
    int t = (int)(r >> 11);
    float v = x[((size_t)b * TLEN + t) * 512 + d];
    __half h, l; split2h(v, h, l);
    hi[i] = h; lo[i] = l;
}

// ---------------- W[K,N] -> Wt fp16 [N,K] (tiled transpose) ------------------
__global__ __launch_bounds__(256)
void conv_wt(const float* __restrict__ W, __half* __restrict__ Wh, int K, int N)
{
    __shared__ float t[32][33];
    const int n0 = blockIdx.x * 32, k0 = blockIdx.y * 32;
    const int tx = threadIdx.x & 31, ty = threadIdx.x >> 5;  // 32x8
#pragma unroll
    for (int j = 0; j < 32; j += 8)
        t[ty + j][tx] = W[(size_t)(k0 + ty + j) * N + n0 + tx];
    __syncthreads();
#pragma unroll
    for (int j = 0; j < 32; j += 8)
        Wh[(size_t)(n0 + ty + j) * K + k0 + tx] = __float2half_rn(t[tx][ty + j]);
}

// ---------------- SRU recurrence ---------------------------------------------
// kcols==4: resid from U col 3.  kcols==3: resid = hhi+hlo (read-before-write,
// same thread owns each element, so in-place update is safe).
// g_out!=nullptr (final layer): skip hi/lo writes, emit time-sum g instead.
__global__ __launch_bounds__(256)
void sru_k(const float* __restrict__ U, const float* __restrict__ vc,
           const float* __restrict__ bvec, int kcols,
           __half* __restrict__ hhi, __half* __restrict__ hlo,
           float* __restrict__ g_out)
{
    const float SCALE_X = 1.7320508075688772f;
    int idx = blockIdx.x * blockDim.x + threadIdx.x;
    int d = idx & (HIDD - 1);
    int b = idx >> 10;
    float vf = vc[d],   vr = vc[HIDD + d];
    float bf = bvec[d], br = bvec[HIDD + d];
    const long kH = (long)kcols * HIDD;
    long ubase = (long)b * kH + d;
    long hbase = (long)b * HIDD + d;
    const long ustride = (long)BSZ * kH;
    const long hstride = (long)BSZ * HIDD;
    float c = 0.f, gsum = 0.f;
#pragma unroll
    for (int t = 0; t < TLEN; t++) {
        float u0 = U[ubase];
        float u1 = U[ubase + HIDD];
        float u2 = U[ubase + 2 * HIDD];
        float xr;
        if (kcols == 4) xr = U[ubase + 3 * HIDD];
        else            xr = __half2float(hhi[hbase]) + __half2float(hlo[hbase]);
        float f = 1.f / (1.f + __expf(-(u1 + vf * c + bf)));
        c = f * c + (1.f - f) * u0;
        float r = 1.f / (1.f + __expf(-(u2 + vr * c + br)));
        float h = r * tanhf(c) + (1.f - r) * xr * SCALE_X;
        if (g_out) {
            gsum += h;
        } else {
            __half hh, hl; split2h(h, hh, hl);
            hhi[hbase] = hh; hlo[hbase] = hl;
        }
        ubase += ustride;
        hbase += hstride;
    }
    if (g_out) g_out[(long)b * HIDD + d] = gsum;
}

// ---------------- FC head ----------------------------------------------------
__global__ __launch_bounds__(128)
void fc_k(const float* __restrict__ g, const float* __restrict__ w,
          const float* __restrict__ bias, float* __restrict__ out)
{
    __shared__ float gs[HIDD];
    int b = blockIdx.x;
    for (int i = threadIdx.x; i < HIDD; i += blockDim.x)
        gs[i] = g[(long)b * HIDD + i];
    __syncthreads();
    int c = threadIdx.x;
    if (c < NCLS) {
        float s = 0.f;
#pragma unroll 8
        for (int hh = 0; hh < HIDD; hh++) s += gs[hh] * w[hh * NCLS + c];
        out[(long)b * NCLS + c] = s * (1.f / TLEN) + bias[c];
    }
}

// ---------------- launch -----------------------------------------------------
extern "C" void kernel_launch(void* const* d_in, const int* in_sizes, int n_in,
                              void* d_out, int out_size)
{
    const float* x    = (const float*)d_in[0];
    const float* W0   = (const float*)d_in[1];
    const float* W1   = (const float*)d_in[2];
    const float* W2   = (const float*)d_in[3];
    const float* vc0  = (const float*)d_in[4];
    const float* vc1  = (const float*)d_in[5];
    const float* vc2  = (const float*)d_in[6];
    const float* b0   = (const float*)d_in[7];
    const float* b1   = (const float*)d_in[8];
    const float* b2   = (const float*)d_in[9];
    const float* fcw  = (const float*)d_in[10];
    const float* fcb  = (const float*)d_in[11];
    float* out = (float*)d_out;

    float *U, *gg;
    __half *ahi, *alo, *wh;
    cudaGetSymbolAddress((void**)&U,   g_U);
    cudaGetSymbolAddress((void**)&gg,  g_g);
    cudaGetSymbolAddress((void**)&ahi, g_ahi);
    cudaGetSymbolAddress((void**)&alo, g_alo);
    cudaGetSymbolAddress((void**)&wh,  g_wh);

    cudaFuncSetAttribute(gemm_tc, cudaFuncAttributeMaxDynamicSharedMemorySize, SMEM_TOTAL);

    const int sruBlocks = (BSZ * HIDD) / 256;

    // Layer 0: x(T,B,512) @ W0(512,4096)
    conv_x<<<(TLEN * BSZ * 512) / 256, 256>>>(x, ahi, alo);
    conv_wt<<<dim3(4096 / 32, 512 / 32), 256>>>(W0, wh, 512, 4096);
    gemm_tc<<<dim3(4096 / BN, MROWS / BM), 512, SMEM_TOTAL>>>(ahi, alo, wh, U, 4096, 512);
    sru_k<<<sruBlocks, 256>>>(U, vc0, b0, 4, ahi, alo, nullptr);

    // Layer 1: h1(=ahi+alo) @ W1(1024,3072)
    conv_wt<<<dim3(3072 / 32, 1024 / 32), 256>>>(W1, wh, 1024, 3072);
    gemm_tc<<<dim3(3072 / BN, MROWS / BM), 512, SMEM_TOTAL>>>(ahi, alo, wh, U, 3072, 1024);
    sru_k<<<sruBlocks, 256>>>(U, vc1, b1, 3, ahi, alo, nullptr);

    // Layer 2: h2(=ahi+alo) @ W2(1024,3072), final SRU emits time-sum g
    conv_wt<<<dim3(3072 / 32, 1024 / 32), 256>>>(W2, wh, 1024, 3072);
    gemm_tc<<<dim3(3072 / BN, MROWS / BM), 512, SMEM_TOTAL>>>(ahi, alo, wh, U, 3072, 1024);
    sru_k<<<sruBlocks, 256>>>(U, vc2, b2, 3, ahi, alo, gg);

    // Head
    fc_k<<<BSZ, 128>>>(gg, fcw, fcb, out);
}

// round 6
// speedup vs baseline: 8.4334x; 1.5366x over previous
#include <cuda_runtime.h>
#include <cuda_fp16.h>
#include <cstdint>

#define BSZ  2048
#define TLEN 12
#define HIDD 1024
#define NCLS 51
#define MROWS (TLEN * BSZ)   // 24576

// GEMM tiling
#define BM 128
#define BN 256
#define BK 64                       // halfs per K-chunk (one 128B row)
#define NSTAGE 4
#define A_STAGE_BYTES 16384         // 128 rows x 128B
#define B_STAGE_BYTES 32768         // 256 rows x 128B
#define STAGE_BYTES (A_STAGE_BYTES + B_STAGE_BYTES)   // 48KB
#define SMEM_TOTAL (NSTAGE * STAGE_BYTES)             // 192KB

// ---------------- scratch (device globals; no allocation allowed) -----------
__device__ __align__(16) float  g_U [(size_t)MROWS * 4096];
__device__ __align__(16) float  g_g [(size_t)BSZ   * HIDD];
__device__ __align__(16) __half g_ah[(size_t)MROWS * HIDD];   // activations fp16
__device__ __align__(16) __half g_wh[(size_t)4096 * HIDD];    // Wt fp16 [N,K]

// ---------------- helpers ----------------------------------------------------
__device__ __forceinline__ uint32_t smem_u32(const void* p) {
    uint32_t a;
    asm("{ .reg .u64 t; cvta.to.shared.u64 t, %1; cvt.u32.u64 %0, t; }" : "=r"(a) : "l"(p));
    return a;
}
#define SWZ(o) ((uint32_t)(o) ^ ((((uint32_t)(o)) >> 3) & 0x70))

__device__ __forceinline__ void cp16(uint32_t s, const void* g) {
    asm volatile("cp.async.cg.shared.global [%0], [%1], 16;" :: "r"(s), "l"(g));
}
#define CP_COMMIT() asm volatile("cp.async.commit_group;" ::: "memory")
#define CP_WAIT2()  asm volatile("cp.async.wait_group 2;" ::: "memory")

#define LDSM4(r, addr) \
    asm volatile("ldmatrix.sync.aligned.m8n8.x4.shared.b16 {%0,%1,%2,%3}, [%4];" \
        : "=r"((r)[0]), "=r"((r)[1]), "=r"((r)[2]), "=r"((r)[3]) : "r"(addr))

#define MMA(d, a, b) \
    asm volatile("mma.sync.aligned.m16n8k16.row.col.f32.f16.f16.f32 " \
        "{%0,%1,%2,%3}, {%4,%5,%6,%7}, {%8,%9}, {%0,%1,%2,%3};" \
        : "+f"((d)[0]), "+f"((d)[1]), "+f"((d)[2]), "+f"((d)[3]) \
        : "r"((a)[0]), "r"((a)[1]), "r"((a)[2]), "r"((a)[3]), "r"((b)[0]), "r"((b)[1]))

// ---------------- mma.sync fp16 GEMM ----------------------------------------
// C[M,N] = A[M,K] @ B[N,K]^T (fp16 in, fp32 accum). grid=(N/BN, M/BM), 512 thr.
__global__ __launch_bounds__(512, 1)
void gemm_tc(const __half* __restrict__ A, const __half* __restrict__ B,
             float* __restrict__ C, int N, int K)
{
    extern __shared__ char smem[];
    const int tid = threadIdx.x, lane = tid & 31, wid = tid >> 5;
    const uint32_t sb = smem_u32(smem);
    const size_t bm = (size_t)blockIdx.y * BM;
    const size_t bn = (size_t)blockIdx.x * BN;
    const int nch = K >> 6;

    // warp -> 64x32 sub-tile
    const int m0w = (wid & 1) * 64;
    const int n0w = (wid >> 1) * 32;
    // ldmatrix lane maps (validated in R4/R5)
    const int rA = lane & 15;
    const int cA = (lane & 16) ? 16 : 0;
    const int rB = (lane & 7) | ((lane & 16) >> 1);
    const int cB = (lane & 8) ? 16 : 0;

    float acc[4][4][4];
#pragma unroll
    for (int i = 0; i < 4; i++)
#pragma unroll
        for (int j = 0; j < 4; j++)
#pragma unroll
            for (int q = 0; q < 4; q++) acc[i][j][q] = 0.f;

    auto loadStage = [&](int c, int s) {
        if (c >= nch) return;
        const int k0 = c << 6;
        const uint32_t sa = sb + s * STAGE_BYTES;
        const uint32_t sB = sa + A_STAGE_BYTES;
        // A: 128 rows x 8 chunks = 1024 cp16
#pragma unroll
        for (int ii = 0; ii < 2; ii++) {
            int i = tid + ii * 512;
            int row = i >> 3, c16 = i & 7;
            cp16(sa + SWZ(row * 128 + c16 * 16),
                 A + (bm + row) * (size_t)K + k0 + c16 * 8);
        }
        // B: 256 rows x 8 chunks = 2048 cp16
#pragma unroll
        for (int ii = 0; ii < 4; ii++) {
            int i = tid + ii * 512;
            int row = i >> 3, c16 = i & 7;
            cp16(sB + SWZ(row * 128 + c16 * 16),
                 B + (bn + row) * (size_t)K + k0 + c16 * 8);
        }
    };

    loadStage(0, 0); CP_COMMIT();
    loadStage(1, 1); CP_COMMIT();
    loadStage(2, 2); CP_COMMIT();

    int stage = 0;
    for (int c = 0; c < nch; c++) {
        CP_WAIT2();                 // chunk c resident (pending <= 2)
        __syncthreads();
        {
            int ws = stage + 3;
            if (ws >= NSTAGE) ws -= NSTAGE;
            loadStage(c + 3, ws);
        }
        CP_COMMIT();

        const uint32_t sa = sb + stage * STAGE_BYTES;
        const uint32_t sB = sa + A_STAGE_BYTES;
        stage = (stage + 1 == NSTAGE) ? 0 : stage + 1;

#pragma unroll
        for (int ks = 0; ks < 4; ks++) {
            uint32_t a[4][4], b[4][2];
#pragma unroll
            for (int np = 0; np < 2; np++) {
                uint32_t r4[4];
                LDSM4(r4, sB + SWZ((n0w + np * 16 + rB) * 128 + ks * 32 + cB));
                b[np * 2][0] = r4[0]; b[np * 2][1] = r4[1];
                b[np * 2 + 1][0] = r4[2]; b[np * 2 + 1][1] = r4[3];
            }
#pragma unroll
            for (int mt = 0; mt < 4; mt++)
                LDSM4(a[mt], sa + SWZ((m0w + mt * 16 + rA) * 128 + ks * 32 + cA));
#pragma unroll
            for (int mt = 0; mt < 4; mt++)
#pragma unroll
                for (int nt = 0; nt < 4; nt++) MMA(acc[mt][nt], a[mt], b[nt]);
        }
    }

    // epilogue
    const int g = lane >> 2, t = lane & 3;
#pragma unroll
    for (int mt = 0; mt < 4; mt++) {
#pragma unroll
        for (int nt = 0; nt < 4; nt++) {
            size_t row = bm + m0w + mt * 16 + g;
            size_t col = bn + n0w + nt * 8 + t * 2;
            *(float2*)(C + row * (size_t)N + col) =
                make_float2(acc[mt][nt][0], acc[mt][nt][1]);
            *(float2*)(C + (row + 8) * (size_t)N + col) =
                make_float2(acc[mt][nt][2], acc[mt][nt][3]);
        }
    }
}

// ---------------- x -> fp16 with (B,T)->(T,B) remap --------------------------
__global__ __launch_bounds__(256)
void conv_x(const float* __restrict__ x, __half* __restrict__ ah)
{
    size_t i = (size_t)blockIdx.x * blockDim.x + threadIdx.x;  // over T*B*512
    int d = i & 511;
    size_t r = i >> 9;
    int b = (int)(r & (BSZ - 1));
    int t = (int)(r >> 11);
    ah[i] = __float2half_rn(x[((size_t)b * TLEN + t) * 512 + d]);
}

// ---------------- W[K,N] -> Wt fp16 [N,K] (tiled transpose) ------------------
__global__ __launch_bounds__(256)
void conv_wt(const float* __restrict__ W, __half* __restrict__ Wh, int K, int N)
{
    __shared__ float t[32][33];
    const int n0 = blockIdx.x * 32, k0 = blockIdx.y * 32;
    const int tx = threadIdx.x & 31, ty = threadIdx.x >> 5;  // 32x8
#pragma unroll
    for (int j = 0; j < 32; j += 8)
        t[ty + j][tx] = W[(size_t)(k0 + ty + j) * N + n0 + tx];
    __syncthreads();
#pragma unroll
    for (int j = 0; j < 32; j += 8)
        Wh[(size_t)(n0 + ty + j) * K + k0 + tx] = __float2half_rn(t[tx][ty + j]);
}

// ---------------- SRU recurrence ---------------------------------------------
// kcols==4: resid from U col 3.  kcols==3: resid = h[..] (fp16, read before
// overwrite; same thread owns each element, so in-place is safe).
// g_out!=nullptr (final layer): skip h writes, emit time-sum g instead.
__global__ __launch_bounds__(256)
void sru_k(const float* __restrict__ U, const float* __restrict__ vc,
           const float* __restrict__ bvec, int kcols,
           __half* __restrict__ hbuf, float* __restrict__ g_out)
{
    const float SCALE_X = 1.7320508075688772f;
    int idx = blockIdx.x * blockDim.x + threadIdx.x;
    int d = idx & (HIDD - 1);
    int b = idx >> 10;
    float vf = vc[d],   vr = vc[HIDD + d];
    float bf = bvec[d], br = bvec[HIDD + d];
    const long kH = (long)kcols * HIDD;
    long ubase = (long)b * kH + d;
    long hbase = (long)b * HIDD + d;
    const long ustride = (long)BSZ * kH;
    const long hstride = (long)BSZ * HIDD;
    float c = 0.f, gsum = 0.f;
#pragma unroll
    for (int t = 0; t < TLEN; t++) {
        float u0 = U[ubase];
        float u1 = U[ubase + HIDD];
        float u2 = U[ubase + 2 * HIDD];
        float xr;
        if (kcols == 4) xr = U[ubase + 3 * HIDD];
        else            xr = __half2float(hbuf[hbase]);
        float f = 1.f / (1.f + __expf(-(u1 + vf * c + bf)));
        c = f * c + (1.f - f) * u0;
        float r = 1.f / (1.f + __expf(-(u2 + vr * c + br)));
        float h = r * tanhf(c) + (1.f - r) * xr * SCALE_X;
        if (g_out) gsum += h;
        else       hbuf[hbase] = __float2half_rn(h);
        ubase += ustride;
        hbase += hstride;
    }
    if (g_out) g_out[(long)b * HIDD + d] = gsum;
}

// ---------------- FC head ----------------------------------------------------
__global__ __launch_bounds__(128)
void fc_k(const float* __restrict__ g, const float* __restrict__ w,
          const float* __restrict__ bias, float* __restrict__ out)
{
    __shared__ float gs[HIDD];
    int b = blockIdx.x;
    for (int i = threadIdx.x; i < HIDD; i += blockDim.x)
        gs[i] = g[(long)b * HIDD + i];
    __syncthreads();
    int c = threadIdx.x;
    if (c < NCLS) {
        float s = 0.f;
#pragma unroll 8
        for (int hh = 0; hh < HIDD; hh++) s += gs[hh] * w[hh * NCLS + c];
        out[(long)b * NCLS + c] = s * (1.f / TLEN) + bias[c];
    }
}

// ---------------- launch -----------------------------------------------------
extern "C" void kernel_launch(void* const* d_in, const int* in_sizes, int n_in,
                              void* d_out, int out_size)
{
    const float* x    = (const float*)d_in[0];
    const float* W0   = (const float*)d_in[1];
    const float* W1   = (const float*)d_in[2];
    const float* W2   = (const float*)d_in[3];
    const float* vc0  = (const float*)d_in[4];
    const float* vc1  = (const float*)d_in[5];
    const float* vc2  = (const float*)d_in[6];
    const float* b0   = (const float*)d_in[7];
    const float* b1   = (const float*)d_in[8];
    const float* b2   = (const float*)d_in[9];
    const float* fcw  = (const float*)d_in[10];
    const float* fcb  = (const float*)d_in[11];
    float* out = (float*)d_out;

    float *U, *gg;
    __half *ah, *wh;
    cudaGetSymbolAddress((void**)&U,  g_U);
    cudaGetSymbolAddress((void**)&gg, g_g);
    cudaGetSymbolAddress((void**)&ah, g_ah);
    cudaGetSymbolAddress((void**)&wh, g_wh);

    cudaFuncSetAttribute(gemm_tc, cudaFuncAttributeMaxDynamicSharedMemorySize, SMEM_TOTAL);

    const int sruBlocks = (BSZ * HIDD) / 256;

    // Layer 0: x(T,B,512) @ W0(512,4096)
    conv_x<<<(TLEN * BSZ * 512) / 256, 256>>>(x, ah);
    conv_wt<<<dim3(4096 / 32, 512 / 32), 256>>>(W0, wh, 512, 4096);
    gemm_tc<<<dim3(4096 / BN, MROWS / BM), 512, SMEM_TOTAL>>>(ah, wh, U, 4096, 512);
    sru_k<<<sruBlocks, 256>>>(U, vc0, b0, 4, ah, nullptr);

    // Layer 1: h1 @ W1(1024,3072)
    conv_wt<<<dim3(3072 / 32, 1024 / 32), 256>>>(W1, wh, 1024, 3072);
    gemm_tc<<<dim3(3072 / BN, MROWS / BM), 512, SMEM_TOTAL>>>(ah, wh, U, 3072, 1024);
    sru_k<<<sruBlocks, 256>>>(U, vc1, b1, 3, ah, nullptr);

    // Layer 2: h2 @ W2(1024,3072), final SRU emits time-sum g
    conv_wt<<<dim3(3072 / 32, 1024 / 32), 256>>>(W2, wh, 1024, 3072);
    gemm_tc<<<dim3(3072 / BN, MROWS / BM), 512, SMEM_TOTAL>>>(ah, wh, U, 3072, 1024);
    sru_k<<<sruBlocks, 256>>>(U, vc2, b2, 3, ah, gg);

    // Head
    fc_k<<<BSZ, 128>>>(gg, fcw, fcb, out);
}

// round 7
// speedup vs baseline: 8.8673x; 1.0515x over previous
#include <cuda_runtime.h>
#include <cuda_fp16.h>
#include <cstdint>

#define BSZ  2048
#define TLEN 12
#define HIDD 1024
#define NCLS 51
#define MROWS (TLEN * BSZ)   // 24576

// GEMM tiling
#define BM 128
#define BN 256
#define NSTAGE 4
#define A_STAGE_BYTES 16384         // 128 rows x 128B
#define B_STAGE_BYTES 32768         // 256 rows x 128B
#define STAGE_BYTES (A_STAGE_BYTES + B_STAGE_BYTES)   // 48KB
#define SMEM_TOTAL (NSTAGE * STAGE_BYTES)             // 192KB

// ---------------- scratch (device globals; no allocation allowed) -----------
__device__ __align__(16) float  g_U32[(size_t)MROWS * 2048];  // u0 (+resid L0) fp32
__device__ __align__(16) __half g_U16[(size_t)MROWS * 2048];  // u1|u2 fp16
__device__ __align__(16) float  g_g  [(size_t)BSZ   * HIDD];
__device__ __align__(16) __half g_ah [(size_t)MROWS * HIDD];  // activations fp16
__device__ __align__(16) __half g_wh [(size_t)4096 * HIDD];   // Wt fp16 [N,K]

// ---------------- helpers ----------------------------------------------------
__device__ __forceinline__ uint32_t smem_u32(const void* p) {
    uint32_t a;
    asm("{ .reg .u64 t; cvta.to.shared.u64 t, %1; cvt.u32.u64 %0, t; }" : "=r"(a) : "l"(p));
    return a;
}
#define SWZ(o) ((uint32_t)(o) ^ ((((uint32_t)(o)) >> 3) & 0x70))

__device__ __forceinline__ void cp16(uint32_t s, const void* g) {
    asm volatile("cp.async.cg.shared.global [%0], [%1], 16;" :: "r"(s), "l"(g));
}
#define CP_COMMIT() asm volatile("cp.async.commit_group;" ::: "memory")
#define CP_WAIT2()  asm volatile("cp.async.wait_group 2;" ::: "memory")

#define LDSM4(r, addr) \
    asm volatile("ldmatrix.sync.aligned.m8n8.x4.shared.b16 {%0,%1,%2,%3}, [%4];" \
        : "=r"((r)[0]), "=r"((r)[1]), "=r"((r)[2]), "=r"((r)[3]) : "r"(addr))

#define MMA(d, a, b) \
    asm volatile("mma.sync.aligned.m16n8k16.row.col.f32.f16.f16.f32 " \
        "{%0,%1,%2,%3}, {%4,%5,%6,%7}, {%8,%9}, {%0,%1,%2,%3};" \
        : "+f"((d)[0]), "+f"((d)[1]), "+f"((d)[2]), "+f"((d)[3]) \
        : "r"((a)[0]), "r"((a)[1]), "r"((a)[2]), "r"((a)[3]), "r"((b)[0]), "r"((b)[1]))

// ---------------- mma.sync fp16 GEMM ----------------------------------------
// U[M,N] = A[M,K] @ B[N,K]^T.  Output split: cols [0,1024) -> U32 (fp32),
// cols [1024,3072) -> U16 (fp16, stride 2048), cols [3072,4096) -> U32+1024.
// w32 = U32 row stride (2048 for layer 0, 1024 otherwise).
__global__ __launch_bounds__(512, 1)
void gemm_tc(const __half* __restrict__ A, const __half* __restrict__ B,
             float* __restrict__ U32, __half* __restrict__ U16,
             int N, int K, int w32)
{
    extern __shared__ char smem[];
    const int tid = threadIdx.x, lane = tid & 31, wid = tid >> 5;
    const uint32_t sb = smem_u32(smem);
    const size_t bm = (size_t)blockIdx.y * BM;
    const size_t bn = (size_t)blockIdx.x * BN;
    const int nch = K >> 6;

    const int m0w = (wid & 1) * 64;
    const int n0w = (wid >> 1) * 32;
    const int rA = lane & 15;
    const int cA = (lane & 16) ? 16 : 0;
    const int rB = (lane & 7) | ((lane & 16) >> 1);
    const int cB = (lane & 8) ? 16 : 0;

    float acc[4][4][4];
#pragma unroll
    for (int i = 0; i < 4; i++)
#pragma unroll
        for (int j = 0; j < 4; j++)
#pragma unroll
            for (int q = 0; q < 4; q++) acc[i][j][q] = 0.f;

    auto loadStage = [&](int c, int s) {
        if (c >= nch) return;
        const int k0 = c << 6;
        const uint32_t sa = sb + s * STAGE_BYTES;
        const uint32_t sB = sa + A_STAGE_BYTES;
#pragma unroll
        for (int ii = 0; ii < 2; ii++) {
            int i = tid + ii * 512;
            int row = i >> 3, c16 = i & 7;
            cp16(sa + SWZ(row * 128 + c16 * 16),
                 A + (bm + row) * (size_t)K + k0 + c16 * 8);
        }
#pragma unroll
        for (int ii = 0; ii < 4; ii++) {
            int i = tid + ii * 512;
            int row = i >> 3, c16 = i & 7;
            cp16(sB + SWZ(row * 128 + c16 * 16),
                 B + (bn + row) * (size_t)K + k0 + c16 * 8);
        }
    };

    loadStage(0, 0); CP_COMMIT();
    loadStage(1, 1); CP_COMMIT();
    loadStage(2, 2); CP_COMMIT();

    int stage = 0;
    for (int c = 0; c < nch; c++) {
        CP_WAIT2();
        __syncthreads();
        {
            int ws = stage + 3;
            if (ws >= NSTAGE) ws -= NSTAGE;
            loadStage(c + 3, ws);
        }
        CP_COMMIT();

        const uint32_t sa = sb + stage * STAGE_BYTES;
        const uint32_t sB = sa + A_STAGE_BYTES;
        stage = (stage + 1 == NSTAGE) ? 0 : stage + 1;

#pragma unroll
        for (int ks = 0; ks < 4; ks++) {
            uint32_t a[4][4], b[4][2];
#pragma unroll
            for (int np = 0; np < 2; np++) {
                uint32_t r4[4];
                LDSM4(r4, sB + SWZ((n0w + np * 16 + rB) * 128 + ks * 32 + cB));
                b[np * 2][0] = r4[0]; b[np * 2][1] = r4[1];
                b[np * 2 + 1][0] = r4[2]; b[np * 2 + 1][1] = r4[3];
            }
#pragma unroll
            for (int mt = 0; mt < 4; mt++)
                LDSM4(a[mt], sa + SWZ((m0w + mt * 16 + rA) * 128 + ks * 32 + cA));
#pragma unroll
            for (int mt = 0; mt < 4; mt++)
#pragma unroll
                for (int nt = 0; nt < 4; nt++) MMA(acc[mt][nt], a[mt], b[nt]);
        }
    }

    // epilogue — block-uniform region (BN=256 divides 1024/3072 boundaries)
    const int g = lane >> 2, t = lane & 3;
    const int region = (bn < 1024) ? 0 : ((bn < 3072) ? 1 : 2);
    if (region == 1) {
        const size_t cb = bn - 1024;
#pragma unroll
        for (int mt = 0; mt < 4; mt++) {
#pragma unroll
            for (int nt = 0; nt < 4; nt++) {
                size_t row = bm + m0w + mt * 16 + g;
                size_t col = cb + n0w + nt * 8 + t * 2;
                *(__half2*)(U16 + row * 2048 + col) =
                    __floats2half2_rn(acc[mt][nt][0], acc[mt][nt][1]);
                *(__half2*)(U16 + (row + 8) * 2048 + col) =
                    __floats2half2_rn(acc[mt][nt][2], acc[mt][nt][3]);
            }
        }
    } else {
        const size_t cb = (region == 0) ? bn : (1024 + (bn - 3072));
#pragma unroll
        for (int mt = 0; mt < 4; mt++) {
#pragma unroll
            for (int nt = 0; nt < 4; nt++) {
                size_t row = bm + m0w + mt * 16 + g;
                size_t col = cb + n0w + nt * 8 + t * 2;
                *(float2*)(U32 + row * (size_t)w32 + col) =
                    make_float2(acc[mt][nt][0], acc[mt][nt][1]);
                *(float2*)(U32 + (row + 8) * (size_t)w32 + col) =
                    make_float2(acc[mt][nt][2], acc[mt][nt][3]);
            }
        }
    }
}

// ---------------- x -> fp16 with (B,T)->(T,B) remap --------------------------
__global__ __launch_bounds__(256)
void conv_x(const float* __restrict__ x, __half* __restrict__ ah)
{
    size_t i = (size_t)blockIdx.x * blockDim.x + threadIdx.x;  // over T*B*512
    int d = i & 511;
    size_t r = i >> 9;
    int b = (int)(r & (BSZ - 1));
    int t = (int)(r >> 11);
    ah[i] = __float2half_rn(x[((size_t)b * TLEN + t) * 512 + d]);
}

// ---------------- W[K,N] -> Wt fp16 [N,K] (tiled transpose) ------------------
__global__ __launch_bounds__(256)
void conv_wt(const float* __restrict__ W, __half* __restrict__ Wh, int K, int N)
{
    __shared__ float t[32][33];
    const int n0 = blockIdx.x * 32, k0 = blockIdx.y * 32;
    const int tx = threadIdx.x & 31, ty = threadIdx.x >> 5;  // 32x8
#pragma unroll
    for (int j = 0; j < 32; j += 8)
        t[ty + j][tx] = W[(size_t)(k0 + ty + j) * N + n0 + tx];
    __syncthreads();
#pragma unroll
    for (int j = 0; j < 32; j += 8)
        Wh[(size_t)(n0 + ty + j) * K + k0 + tx] = __float2half_rn(t[tx][ty + j]);
}

// ---------------- SRU recurrence (2-wide vectorized) -------------------------
// u0 fp32 in U32 (+resid at col offset 1024 if resid_in_u), u1|u2 fp16 in U16.
// resid otherwise read from hbuf (fp16, in-place overwrite, same thread owns it).
// g_out!=nullptr (final layer): emit time-sum instead of h.
__global__ __launch_bounds__(256)
void sru_k(const float* __restrict__ U32, const __half* __restrict__ U16,
           int w32, int resid_in_u,
           const float* __restrict__ vc, const float* __restrict__ bvec,
           __half* __restrict__ hbuf, float* __restrict__ g_out)
{
    const float SCALE_X = 1.7320508075688772f;
    int idx = blockIdx.x * blockDim.x + threadIdx.x;  // over BSZ*512
    int d = (idx & 511) * 2;
    int b = idx >> 9;
    float2 vf = *(const float2*)(vc + d);
    float2 vr = *(const float2*)(vc + HIDD + d);
    float2 bf = *(const float2*)(bvec + d);
    float2 br = *(const float2*)(bvec + HIDD + d);
    float cx = 0.f, cy = 0.f, gx = 0.f, gy = 0.f;
#pragma unroll
    for (int t = 0; t < TLEN; t++) {
        size_t row = (size_t)t * BSZ + b;
        float2 u0 = *(const float2*)(U32 + row * (size_t)w32 + d);
        float2 u1 = __half22float2(*(const __half2*)(U16 + row * 2048 + d));
        float2 u2 = __half22float2(*(const __half2*)(U16 + row * 2048 + 1024 + d));
        float2 xr;
        if (resid_in_u) xr = *(const float2*)(U32 + row * (size_t)w32 + 1024 + d);
        else            xr = __half22float2(*(const __half2*)(hbuf + row * HIDD + d));

        float fx = 1.f / (1.f + __expf(-(u1.x + vf.x * cx + bf.x)));
        float fy = 1.f / (1.f + __expf(-(u1.y + vf.y * cy + bf.y)));
        cx = fx * cx + (1.f - fx) * u0.x;
        cy = fy * cy + (1.f - fy) * u0.y;
        float rx = 1.f / (1.f + __expf(-(u2.x + vr.x * cx + br.x)));
        float ry = 1.f / (1.f + __expf(-(u2.y + vr.y * cy + br.y)));
        float hx = rx * tanhf(cx) + (1.f - rx) * xr.x * SCALE_X;
        float hy = ry * tanhf(cy) + (1.f - ry) * xr.y * SCALE_X;
        if (g_out) { gx += hx; gy += hy; }
        else *(__half2*)(hbuf + row * HIDD + d) = __floats2half2_rn(hx, hy);
    }
    if (g_out) *(float2*)(g_out + (size_t)b * HIDD + d) = make_float2(gx, gy);
}

// ---------------- FC head ----------------------------------------------------
__global__ __launch_bounds__(128)
void fc_k(const float* __restrict__ g, const float* __restrict__ w,
          const float* __restrict__ bias, float* __restrict__ out)
{
    __shared__ float gs[HIDD];
    int b = blockIdx.x;
    for (int i = threadIdx.x; i < HIDD; i += blockDim.x)
        gs[i] = g[(long)b * HIDD + i];
    __syncthreads();
    int c = threadIdx.x;
    if (c < NCLS) {
        float s = 0.f;
#pragma unroll 8
        for (int hh = 0; hh < HIDD; hh++) s += gs[hh] * w[hh * NCLS + c];
        out[(long)b * NCLS + c] = s * (1.f / TLEN) + bias[c];
    }
}

// ---------------- launch -----------------------------------------------------
extern "C" void kernel_launch(void* const* d_in, const int* in_sizes, int n_in,
                              void* d_out, int out_size)
{
    const float* x    = (const float*)d_in[0];
    const float* W0   = (const float*)d_in[1];
    const float* W1   = (const float*)d_in[2];
    const float* W2   = (const float*)d_in[3];
    const float* vc0  = (const float*)d_in[4];
    const float* vc1  = (const float*)d_in[5];
    const float* vc2  = (const float*)d_in[6];
    const float* b0   = (const float*)d_in[7];
    const float* b1   = (const float*)d_in[8];
    const float* b2   = (const float*)d_in[9];
    const float* fcw  = (const float*)d_in[10];
    const float* fcb  = (const float*)d_in[11];
    float* out = (float*)d_out;

    float *U32, *gg;
    __half *U16, *ah, *wh;
    cudaGetSymbolAddress((void**)&U32, g_U32);
    cudaGetSymbolAddress((void**)&U16, g_U16);
    cudaGetSymbolAddress((void**)&gg,  g_g);
    cudaGetSymbolAddress((void**)&ah,  g_ah);
    cudaGetSymbolAddress((void**)&wh,  g_wh);

    cudaFuncSetAttribute(gemm_tc, cudaFuncAttributeMaxDynamicSharedMemorySize, SMEM_TOTAL);

    const int sruBlocks = (BSZ * 512) / 256;

    // Layer 0: x(T,B,512) @ W0(512,4096); u0+resid fp32 (w32=2048), u1|u2 fp16
    conv_x<<<(TLEN * BSZ * 512) / 256, 256>>>(x, ah);
    conv_wt<<<dim3(4096 / 32, 512 / 32), 256>>>(W0, wh, 512, 4096);
    gemm_tc<<<dim3(4096 / BN, MROWS / BM), 512, SMEM_TOTAL>>>(ah, wh, U32, U16, 4096, 512, 2048);
    sru_k<<<sruBlocks, 256>>>(U32, U16, 2048, 1, vc0, b0, ah, nullptr);

    // Layer 1: h1 @ W1(1024,3072); u0 fp32 (w32=1024), u1|u2 fp16
    conv_wt<<<dim3(3072 / 32, 1024 / 32), 256>>>(W1, wh, 1024, 3072);
    gemm_tc<<<dim3(3072 / BN, MROWS / BM), 512, SMEM_TOTAL>>>(ah, wh, U32, U16, 3072, 1024, 1024);
    sru_k<<<sruBlocks, 256>>>(U32, U16, 1024, 0, vc1, b1, ah, nullptr);

    // Layer 2: h2 @ W2(1024,3072); final SRU emits time-sum g
    conv_wt<<<dim3(3072 / 32, 1024 / 32), 256>>>(W2, wh, 1024, 3072);
    gemm_tc<<<dim3(3072 / BN, MROWS / BM), 512, SMEM_TOTAL>>>(ah, wh, U32, U16, 3072, 1024, 1024);
    sru_k<<<sruBlocks, 256>>>(U32, U16, 1024, 0, vc2, b2, ah, gg);

    // Head
    fc_k<<<BSZ, 128>>>(gg, fcw, fcb, out);
}

// round 9
// speedup vs baseline: 9.3715x; 1.0569x over previous
#include <cuda_runtime.h>
#include <cuda_fp16.h>
#include <cstdint>

#define BSZ  2048
#define TLEN 12
#define HIDD 1024
#define NCLS 51
#define MROWS (TLEN * BSZ)   // 24576

// GEMM tiling: 128x128 CTA tile, 256 threads, 2 CTAs/SM
#define BM 128
#define BN 128
#define NSTAGE 3
#define A_STAGE_BYTES 16384         // 128 rows x 128B
#define B_STAGE_BYTES 16384         // 128 rows x 128B
#define STAGE_BYTES (A_STAGE_BYTES + B_STAGE_BYTES)   // 32KB
#define SMEM_TOTAL (NSTAGE * STAGE_BYTES)             // 96KB

// ---------------- scratch (device globals; no allocation allowed) -----------
__device__ __align__(16) float  g_U32[(size_t)MROWS * 2048];  // u0 (+resid L0) fp32
__device__ __align__(16) __half g_U16[(size_t)MROWS * 2048];  // u1|u2 fp16
__device__ __align__(16) float  g_g  [(size_t)BSZ   * HIDD];
__device__ __align__(16) __half g_ah [(size_t)MROWS * HIDD];  // activations fp16
__device__ __align__(16) __half g_wh [(size_t)4096 * HIDD];   // Wt fp16 [N,K]

// ---------------- helpers ----------------------------------------------------
__device__ __forceinline__ uint32_t smem_u32(const void* p) {
    uint32_t a;
    asm("{ .reg .u64 t; cvta.to.shared.u64 t, %1; cvt.u32.u64 %0, t; }" : "=r"(a) : "l"(p));
    return a;
}
#define SWZ(o) ((uint32_t)(o) ^ ((((uint32_t)(o)) >> 3) & 0x70))

__device__ __forceinline__ void cp16(uint32_t s, const void* g) {
    asm volatile("cp.async.cg.shared.global [%0], [%1], 16;" :: "r"(s), "l"(g));
}
#define CP_COMMIT() asm volatile("cp.async.commit_group;" ::: "memory")
#define CP_WAIT1()  asm volatile("cp.async.wait_group 1;" ::: "memory")

#define LDSM4(r, addr) \
    asm volatile("ldmatrix.sync.aligned.m8n8.x4.shared.b16 {%0,%1,%2,%3}, [%4];" \
        : "=r"((r)[0]), "=r"((r)[1]), "=r"((r)[2]), "=r"((r)[3]) : "r"(addr))

#define MMA(d, a, b) \
    asm volatile("mma.sync.aligned.m16n8k16.row.col.f32.f16.f16.f32 " \
        "{%0,%1,%2,%3}, {%4,%5,%6,%7}, {%8,%9}, {%0,%1,%2,%3};" \
        : "+f"((d)[0]), "+f"((d)[1]), "+f"((d)[2]), "+f"((d)[3]) \
        : "r"((a)[0]), "r"((a)[1]), "r"((a)[2]), "r"((a)[3]), "r"((b)[0]), "r"((b)[1]))

// ---------------- mma.sync fp16 GEMM ----------------------------------------
// U[M,N] = A[M,K] @ B[N,K]^T.  Output split: cols [0,1024) -> U32 (fp32),
// cols [1024,3072) -> U16 (fp16, stride 2048), cols [3072,4096) -> U32+1024.
// w32 = U32 row stride (2048 for layer 0, 1024 otherwise).
__global__ __launch_bounds__(256, 2)
void gemm_tc(const __half* __restrict__ A, const __half* __restrict__ B,
             float* __restrict__ U32, __half* __restrict__ U16,
             int N, int K, int w32)
{
    extern __shared__ char smem[];
    const int tid = threadIdx.x, lane = tid & 31, wid = tid >> 5;
    const uint32_t sb = smem_u32(smem);
    const size_t bm = (size_t)blockIdx.y * BM;
    const size_t bn = (size_t)blockIdx.x * BN;
    const int nch = K >> 6;

    // 8 warps: 2 (M) x 4 (N); warp tile 64x32
    const int m0w = (wid & 1) * 64;
    const int n0w = (wid >> 1) * 32;
    const int rA = lane & 15;
    const int cA = (lane & 16) ? 16 : 0;
    const int rB = (lane & 7) | ((lane & 16) >> 1);
    const int cB = (lane & 8) ? 16 : 0;

    float acc[4][4][4];
#pragma unroll
    for (int i = 0; i < 4; i++)
#pragma unroll
        for (int j = 0; j < 4; j++)
#pragma unroll
            for (int q = 0; q < 4; q++) acc[i][j][q] = 0.f;

    auto loadStage = [&](int c, int s) {
        if (c >= nch) return;
        const int k0 = c << 6;
        const uint32_t sa = sb + s * STAGE_BYTES;
        const uint32_t sB = sa + A_STAGE_BYTES;
#pragma unroll
        for (int ii = 0; ii < 4; ii++) {
            int i = tid + ii * 256;
            int row = i >> 3, c16 = i & 7;
            cp16(sa + SWZ(row * 128 + c16 * 16),
                 A + (bm + row) * (size_t)K + k0 + c16 * 8);
        }
#pragma unroll
        for (int ii = 0; ii < 4; ii++) {
            int i = tid + ii * 256;
            int row = i >> 3, c16 = i & 7;
            cp16(sB + SWZ(row * 128 + c16 * 16),
                 B + (bn + row) * (size_t)K + k0 + c16 * 8);
        }
    };

    loadStage(0, 0); CP_COMMIT();
    loadStage(1, 1); CP_COMMIT();

    int stage = 0;
    for (int c = 0; c < nch; c++) {
        CP_WAIT1();                 // chunk c resident (pending <= 1)
        __syncthreads();
        {
            int ws = stage + 2;     // distance-2 prefetch: distinct from c and c+1
            if (ws >= NSTAGE) ws -= NSTAGE;
            loadStage(c + 2, ws);
        }
        CP_COMMIT();

        const uint32_t sa = sb + stage * STAGE_BYTES;
        const uint32_t sB = sa + A_STAGE_BYTES;
        stage = (stage + 1 == NSTAGE) ? 0 : stage + 1;

#pragma unroll
        for (int ks = 0; ks < 4; ks++) {
            uint32_t a[4][4], b[4][2];
#pragma unroll
            for (int np = 0; np < 2; np++) {
                uint32_t r4[4];
                LDSM4(r4, sB + SWZ((n0w + np * 16 + rB) * 128 + ks * 32 + cB));
                b[np * 2][0] = r4[0]; b[np * 2][1] = r4[1];
                b[np * 2 + 1][0] = r4[2]; b[np * 2 + 1][1] = r4[3];
            }
#pragma unroll
            for (int mt = 0; mt < 4; mt++)
                LDSM4(a[mt], sa + SWZ((m0w + mt * 16 + rA) * 128 + ks * 32 + cA));
#pragma unroll
            for (int mt = 0; mt < 4; mt++)
#pragma unroll
                for (int nt = 0; nt < 4; nt++) MMA(acc[mt][nt], a[mt], b[nt]);
        }
    }

    // epilogue — block-uniform region (BN=128 divides 1024/3072 boundaries)
    const int g = lane >> 2, t = lane & 3;
    const int region = (bn < 1024) ? 0 : ((bn < 3072) ? 1 : 2);
    if (region == 1) {
        const size_t cb = bn - 1024;
#pragma unroll
        for (int mt = 0; mt < 4; mt++) {
#pragma unroll
            for (int nt = 0; nt < 4; nt++) {
                size_t row = bm + m0w + mt * 16 + g;
                size_t col = cb + n0w + nt * 8 + t * 2;
                *(__half2*)(U16 + row * 2048 + col) =
                    __floats2half2_rn(acc[mt][nt][0], acc[mt][nt][1]);
                *(__half2*)(U16 + (row + 8) * 2048 + col) =
                    __floats2half2_rn(acc[mt][nt][2], acc[mt][nt][3]);
            }
        }
    } else {
        const size_t cb = (region == 0) ? bn : (1024 + (bn - 3072));
#pragma unroll
        for (int mt = 0; mt < 4; mt++) {
#pragma unroll
            for (int nt = 0; nt < 4; nt++) {
                size_t row = bm + m0w + mt * 16 + g;
                size_t col = cb + n0w + nt * 8 + t * 2;
                *(float2*)(U32 + row * (size_t)w32 + col) =
                    make_float2(acc[mt][nt][0], acc[mt][nt][1]);
                *(float2*)(U32 + (row + 8) * (size_t)w32 + col) =
                    make_float2(acc[mt][nt][2], acc[mt][nt][3]);
            }
        }
    }
}

// ---------------- x -> fp16 with (B,T)->(T,B) remap --------------------------
__global__ __launch_bounds__(256)
void conv_x(const float* __restrict__ x, __half* __restrict__ ah)
{
    size_t i = (size_t)blockIdx.x * blockDim.x + threadIdx.x;  // over T*B*512
    int d = i & 511;
    size_t r = i >> 9;
    int b = (int)(r & (BSZ - 1));
    int t = (int)(r >> 11);
    ah[i] = __float2half_rn(x[((size_t)b * TLEN + t) * 512 + d]);
}

// ---------------- W[K,N] -> Wt fp16 [N,K] (tiled transpose) ------------------
__global__ __launch_bounds__(256)
void conv_wt(const float* __restrict__ W, __half* __restrict__ Wh, int K, int N)
{
    __shared__ float t[32][33];
    const int n0 = blockIdx.x * 32, k0 = blockIdx.y * 32;
    const int tx = threadIdx.x & 31, ty = threadIdx.x >> 5;  // 32x8
#pragma unroll
    for (int j = 0; j < 32; j += 8)
        t[ty + j][tx] = W[(size_t)(k0 + ty + j) * N + n0 + tx];
    __syncthreads();
#pragma unroll
    for (int j = 0; j < 32; j += 8)
        Wh[(size_t)(n0 + ty + j) * K + k0 + tx] = __float2half_rn(t[tx][ty + j]);
}

// ---------------- SRU recurrence (2-wide, software-pipelined) ----------------
// u0 fp32 in U32 (+resid at col offset 1024 if resid_in_u), u1|u2 fp16 in U16.
// resid otherwise from hbuf (fp16, in-place overwrite, same thread owns it).
// g_out!=nullptr (final layer): emit time-sum instead of h.
__global__ __launch_bounds__(256)
void sru_k(const float* __restrict__ U32, const __half* __restrict__ U16,
           int w32, int resid_in_u,
           const float* __restrict__ vc, const float* __restrict__ bvec,
           __half* __restrict__ hbuf, float* __restrict__ g_out)
{
    const float SCALE_X = 1.7320508075688772f;
    int idx = blockIdx.x * blockDim.x + threadIdx.x;  // over BSZ*512
    int d = (idx & 511) * 2;
    int b = idx >> 9;
    float2 vf = *(const float2*)(vc + d);
    float2 vr = *(const float2*)(vc + HIDD + d);
    float2 bf = *(const float2*)(bvec + d);
    float2 br = *(const float2*)(bvec + HIDD + d);
    float cx = 0.f, cy = 0.f, gx = 0.f, gy = 0.f;

    // prefetch t=0
    float2 u0 = *(const float2*)(U32 + (size_t)b * w32 + d);
    __half2 u1h = *(const __half2*)(U16 + (size_t)b * 2048 + d);
    __half2 u2h = *(const __half2*)(U16 + (size_t)b * 2048 + 1024 + d);
    float2 xr;
    if (resid_in_u) xr = *(const float2*)(U32 + (size_t)b * w32 + 1024 + d);
    else            xr = __half22float2(*(const __half2*)(hbuf + (size_t)b * HIDD + d));

#pragma unroll
    for (int t = 0; t < TLEN; t++) {
        float2 u0n = u0, xrn = xr; __half2 u1n = u1h, u2n = u2h;
        if (t + 1 < TLEN) {
            size_t rn = (size_t)(t + 1) * BSZ + b;
            u0n = *(const float2*)(U32 + rn * w32 + d);
            u1n = *(const __half2*)(U16 + rn * 2048 + d);
            u2n = *(const __half2*)(U16 + rn * 2048 + 1024 + d);
            if (resid_in_u) xrn = *(const float2*)(U32 + rn * w32 + 1024 + d);
            else            xrn = __half22float2(*(const __half2*)(hbuf + rn * HIDD + d));
        }
        float2 u1 = __half22float2(u1h);
        float2 u2 = __half22float2(u2h);
        float fx = 1.f / (1.f + __expf(-(u1.x + vf.x * cx + bf.x)));
        float fy = 1.f / (1.f + __expf(-(u1.y + vf.y * cy + bf.y)));
        cx = fx * cx + (1.f - fx) * u0.x;
        cy = fy * cy + (1.f - fy) * u0.y;
        float rx = 1.f / (1.f + __expf(-(u2.x + vr.x * cx + br.x)));
        float ry = 1.f / (1.f + __expf(-(u2.y + vr.y * cy + br.y)));
        float hx = rx * tanhf(cx) + (1.f - rx) * xr.x * SCALE_X;
        float hy = ry * tanhf(cy) + (1.f - ry) * xr.y * SCALE_X;
        if (g_out) { gx += hx; gy += hy; }
        else *(__half2*)(hbuf + ((size_t)t * BSZ + b) * HIDD + d) = __floats2half2_rn(hx, hy);
        u0 = u0n; u1h = u1n; u2h = u2n; xr = xrn;
    }
    if (g_out) *(float2*)(g_out + (size_t)b * HIDD + d) = make_float2(gx, gy);
}

// ---------------- FC head ----------------------------------------------------
__global__ __launch_bounds__(128)
void fc_k(const float* __restrict__ g, const float* __restrict__ w,
          const float* __restrict__ bias, float* __restrict__ out)
{
    __shared__ float gs[HIDD];
    int b = blockIdx.x;
    for (int i = threadIdx.x; i < HIDD; i += blockDim.x)
        gs[i] = g[(long)b * HIDD + i];
    __syncthreads();
    int c = threadIdx.x;
    if (c < NCLS) {
        float s = 0.f;
#pragma unroll 8
        for (int hh = 0; hh < HIDD; hh++) s += gs[hh] * w[hh * NCLS + c];
        out[(long)b * NCLS + c] = s * (1.f / TLEN) + bias[c];
    }
}

// ---------------- launch -----------------------------------------------------
extern "C" void kernel_launch(void* const* d_in, const int* in_sizes, int n_in,
                              void* d_out, int out_size)
{
    const float* x    = (const float*)d_in[0];
    const float* W0   = (const float*)d_in[1];
    const float* W1   = (const float*)d_in[2];
    const float* W2   = (const float*)d_in[3];
    const float* vc0  = (const float*)d_in[4];
    const float* vc1  = (const float*)d_in[5];
    const float* vc2  = (const float*)d_in[6];
    const float* b0   = (const float*)d_in[7];
    const float* b1   = (const float*)d_in[8];
    const float* b2   = (const float*)d_in[9];
    const float* fcw  = (const float*)d_in[10];
    const float* fcb  = (const float*)d_in[11];
    float* out = (float*)d_out;

    float *U32, *gg;
    __half *U16, *ah, *wh;
    cudaGetSymbolAddress((void**)&U32, g_U32);
    cudaGetSymbolAddress((void**)&U16, g_U16);
    cudaGetSymbolAddress((void**)&gg,  g_g);
    cudaGetSymbolAddress((void**)&ah,  g_ah);
    cudaGetSymbolAddress((void**)&wh,  g_wh);

    cudaFuncSetAttribute(gemm_tc, cudaFuncAttributeMaxDynamicSharedMemorySize, SMEM_TOTAL);

    const int sruBlocks = (BSZ * 512) / 256;

    // Layer 0: x(T,B,512) @ W0(512,4096); u0+resid fp32 (w32=2048), u1|u2 fp16
    conv_x<<<(TLEN * BSZ * 512) / 256, 256>>>(x, ah);
    conv_wt<<<dim3(4096 / 32, 512 / 32), 256>>>(W0, wh, 512, 4096);
    gemm_tc<<<dim3(4096 / BN, MROWS / BM), 256, SMEM_TOTAL>>>(ah, wh, U32, U16, 4096, 512, 2048);
    sru_k<<<sruBlocks, 256>>>(U32, U16, 2048, 1, vc0, b0, ah, nullptr);

    // Layer 1: h1 @ W1(1024,3072); u0 fp32 (w32=1024), u1|u2 fp16
    conv_wt<<<dim3(3072 / 32, 1024 / 32), 256>>>(W1, wh, 1024, 3072);
    gemm_tc<<<dim3(3072 / BN, MROWS / BM), 256, SMEM_TOTAL>>>(ah, wh, U32, U16, 3072, 1024, 1024);
    sru_k<<<sruBlocks, 256>>>(U32, U16, 1024, 0, vc1, b1, ah, nullptr);

    // Layer 2: h2 @ W2(1024,3072); final SRU emits time-sum g
    conv_wt<<<dim3(3072 / 32, 1024 / 32), 256>>>(W2, wh, 1024, 3072);
    gemm_tc<<<dim3(3072 / BN, MROWS / BM), 256, SMEM_TOTAL>>>(ah, wh, U32, U16, 3072, 1024, 1024);
    sru_k<<<sruBlocks, 256>>>(U32, U16, 1024, 0, vc2, b2, ah, gg);

    // Head
    fc_k<<<BSZ, 128>>>(gg, fcw, fcb, out);
}